// round 4
// baseline (speedup 1.0000x reference)
#include <cuda_runtime.h>

// DynamicConv: B=64, CIN=COUT=256, K=4 experts, 3x3 kernel on (L=1024 x 1) input.
// Width==1 with padding 1 => only kw=1 column of the kernel contributes:
//   out[b,o,h] = sum_{i,kh} Wagg[b,o,i,kh] * x[b,i,h-1+kh] + aggb[b,o]
//   Wagg[b]    = sum_k att[b,k] * weight[k,:,:,:,1]
//   att        = softmax( relu(cond @ w1^T) @ w2^T / 30 )

#define BATCH   64
#define CIN     256
#define COUT    256
#define CS      256
#define KEXP    4
#define HIDDEN  64
#define LEN     1024
#define TEMP    30.0f

// conv tiling
#define TH      512     // h per CTA
#define TO      32      // cout per CTA
#define CCH     16      // cin chunk
#define SXSTR   (TH + 2)

// scratch (__device__ globals: no allocation allowed)
__device__ float g_att[BATCH * KEXP];
// Wt[k][ci][kh][o] : transposed kw=1 slice, contiguous in o for coalesced mixture loads
__device__ float g_wt[KEXP * CIN * 3 * COUT];

// ---------------------------------------------------------------------------
// Kernel 1: routing MLP + softmax.  64 blocks x 64 threads.
// ---------------------------------------------------------------------------
__global__ void routing_kernel(const float* __restrict__ cond,
                               const float* __restrict__ w1,
                               const float* __restrict__ w2) {
    __shared__ float sh[HIDDEN];
    __shared__ float sl[KEXP];
    const int b = blockIdx.x;
    const int j = threadIdx.x;

    const float* crow = cond + b * CS;
    const float* w1r  = w1 + j * CS;
    float s = 0.0f;
#pragma unroll 8
    for (int i = 0; i < CS; ++i) s = fmaf(crow[i], w1r[i], s);
    sh[j] = fmaxf(s, 0.0f);
    __syncthreads();

    if (j < KEXP) {
        const float* w2r = w2 + j * HIDDEN;
        float t = 0.0f;
#pragma unroll 8
        for (int i = 0; i < HIDDEN; ++i) t = fmaf(sh[i], w2r[i], t);
        sl[j] = t * (1.0f / TEMP);
    }
    __syncthreads();

    if (j == 0) {
        float m = sl[0];
#pragma unroll
        for (int k = 1; k < KEXP; ++k) m = fmaxf(m, sl[k]);
        float e[KEXP];
        float sum = 0.0f;
#pragma unroll
        for (int k = 0; k < KEXP; ++k) { e[k] = expf(sl[k] - m); sum += e[k]; }
        float inv = 1.0f / sum;
#pragma unroll
        for (int k = 0; k < KEXP; ++k) g_att[b * KEXP + k] = e[k] * inv;
    }
}

// ---------------------------------------------------------------------------
// Kernel 2: transpose the kw=1 slice of weight into Wt[k][ci][kh][o].
// ---------------------------------------------------------------------------
__global__ void build_wt_kernel(const float* __restrict__ weight) {
    const int i  = blockIdx.x * 256 + threadIdx.x;     // grid sized exactly
    const int o  = i & (COUT - 1);
    const int t  = i >> 8;           // = (k*CIN + ci)*3 + kh
    const int kh = t % 3;
    const int t2 = t / 3;            // = k*CIN + ci
    const int ci = t2 & (CIN - 1);
    const int k  = t2 >> 8;
    // weight layout: [k][o][ci][kh][kw], kw=1
    g_wt[i] = weight[(((k * COUT + o) * CIN + ci) * 3 + kh) * 3 + 1];
}

// ---------------------------------------------------------------------------
// Kernel 3: the conv.  grid (2 h-tiles, 8 o-tiles, 64 batches), 256 threads.
// Thread = (og = tid>>5 -> 4 couts, hg = tid&31 -> 16 h values strided by 32).
// Warp shares one cout-quad (weight reads broadcast); SMEM x reads are
// conflict-free (consecutive lanes -> consecutive banks).
// ---------------------------------------------------------------------------
__global__ void __launch_bounds__(256, 2)
conv_kernel(const float* __restrict__ x,
            const float* __restrict__ bias,
            float* __restrict__ out) {
    __shared__ float s_x[CCH * SXSTR];     // x chunk with halo, 32.9 KB
    __shared__ float s_w[CCH * 3 * TO];    // mixed weights [ci][kh][o], 6 KB

    const int tid    = threadIdx.x;
    const int hg     = tid & 31;
    const int og4    = (tid >> 5) * 4;
    const int h_base = blockIdx.x * TH;
    const int o_base = blockIdx.y * TO;
    const int b      = blockIdx.z;

    float att4[KEXP];
#pragma unroll
    for (int k = 0; k < KEXP; ++k) att4[k] = g_att[b * KEXP + k];

    const float* xb = x + (size_t)b * CIN * LEN;

    float acc[4][16];
#pragma unroll
    for (int u = 0; u < 4; ++u)
#pragma unroll
        for (int r = 0; r < 16; ++r) acc[u][r] = 0.0f;

    for (int cb = 0; cb < CIN; cb += CCH) {
        __syncthreads();   // previous iteration's smem reads done

        // stage x chunk (with 1-element halo each side), zero-padded at edges
        for (int i = tid; i < CCH * SXSTR; i += 256) {
            int ci = i / SXSTR;
            int hh = i - ci * SXSTR;
            int hs = h_base - 1 + hh;
            float v = 0.0f;
            if ((unsigned)hs < (unsigned)LEN) v = xb[(cb + ci) * LEN + hs];
            s_x[i] = v;
        }

        // mix expert weights for this (cout tile, cin chunk): coalesced in o
        for (int i = tid; i < CCH * 3 * TO; i += 256) {
            int o  = i & (TO - 1);
            int t  = i >> 5;          // = ci*3 + kh
            int kh = t % 3;
            int ci = t / 3;
            const float* wp = g_wt + ((cb + ci) * 3 + kh) * COUT + o_base + o;
            float v = att4[0] * wp[0 * CIN * 3 * COUT]
                    + att4[1] * wp[1 * CIN * 3 * COUT]
                    + att4[2] * wp[2 * CIN * 3 * COUT]
                    + att4[3] * wp[3 * CIN * 3 * COUT];
            s_w[i] = v;
        }
        __syncthreads();

#pragma unroll 2
        for (int ci = 0; ci < CCH; ++ci) {
            float w[4][3];
#pragma unroll
            for (int u = 0; u < 4; ++u)
#pragma unroll
                for (int kh = 0; kh < 3; ++kh)
                    w[u][kh] = s_w[(ci * 3 + kh) * TO + og4 + u];   // broadcast

            const float* xr = s_x + ci * SXSTR + hg;
#pragma unroll
            for (int r = 0; r < 16; ++r) {
                float a = xr[r * 32 + 0];
                float m = xr[r * 32 + 1];
                float c = xr[r * 32 + 2];
#pragma unroll
                for (int u = 0; u < 4; ++u)
                    acc[u][r] = fmaf(w[u][0], a,
                                fmaf(w[u][1], m,
                                fmaf(w[u][2], c, acc[u][r])));
            }
        }
    }

    // epilogue: add mixed bias, store (coalesced: lanes -> consecutive h)
#pragma unroll
    for (int u = 0; u < 4; ++u) {
        const int o = o_base + og4 + u;
        float bs = 0.0f;
#pragma unroll
        for (int k = 0; k < KEXP; ++k) bs = fmaf(att4[k], bias[k * COUT + o], bs);
        float* op = out + ((size_t)(b * COUT + o)) * LEN + h_base + hg;
#pragma unroll
        for (int r = 0; r < 16; ++r) op[r * 32] = acc[u][r] + bs;
    }
}

// ---------------------------------------------------------------------------
extern "C" void kernel_launch(void* const* d_in, const int* in_sizes, int n_in,
                              void* d_out, int out_size) {
    const float* x      = (const float*)d_in[0];   // (64,256,1024,1)
    const float* cond   = (const float*)d_in[1];   // (64,256)
    const float* w1     = (const float*)d_in[2];   // (64,256)
    const float* w2     = (const float*)d_in[3];   // (4,64)
    const float* weight = (const float*)d_in[4];   // (4,256,256,3,3)
    const float* bias   = (const float*)d_in[5];   // (4,256)
    float* out = (float*)d_out;                    // (64,256,1024,1)

    routing_kernel<<<BATCH, HIDDEN>>>(cond, w1, w2);
    build_wt_kernel<<<(KEXP * CIN * 3 * COUT) / 256, 256>>>(weight);
    conv_kernel<<<dim3(LEN / TH, COUT / TO, BATCH), 256>>>(x, bias, out);
}

// round 5
// speedup vs baseline: 1.3084x; 1.3084x over previous
#include <cuda_runtime.h>
#include <cstdint>

// DynamicConv: B=64, CIN=COUT=256, K=4 experts, 3x3 kernel on (L=1024 x 1).
// Width==1 + padding 1 => only the kw=1 column contributes: a 1-D 3-tap conv.
//   out[b,o,h] = sum_{i,kh} Wagg[b,o,i,kh] * x[b,i,h-1+kh] + aggb[b,o]
// This version packs adjacent h pairs and uses Blackwell fma.rn.f32x2 (FFMA2),
// halving FMA-pipe issue count vs the scalar-FFMA round-3 kernel.

#define BATCH   64
#define CIN     256
#define COUT    256
#define CS      256
#define KEXP    4
#define HIDDEN  64
#define LEN     1024
#define TEMP    30.0f

// conv tiling
#define TH      512          // h per CTA
#define TO      32           // cout per CTA
#define CCH     8            // cin chunk (halved: two smem x copies)
#define SXSTR   (TH + 2)     // 514

__device__ float g_att[BATCH * KEXP];
// Wt[k][ci][kh][o] : transposed kw=1 slice, contiguous in o
__device__ float g_wt[KEXP * CIN * 3 * COUT];

// ---------------------------------------------------------------------------
// packed fp32x2 helpers
// ---------------------------------------------------------------------------
__device__ __forceinline__ unsigned long long fma2(unsigned long long a,
                                                   unsigned long long b,
                                                   unsigned long long c) {
    unsigned long long d;
    asm("fma.rn.f32x2 %0, %1, %2, %3;" : "=l"(d) : "l"(a), "l"(b), "l"(c));
    return d;
}
__device__ __forceinline__ unsigned long long splat2(float w) {
    unsigned long long d;
    unsigned int u = __float_as_uint(w);
    asm("mov.b64 %0, {%1, %1};" : "=l"(d) : "r"(u));
    return d;
}

// ---------------------------------------------------------------------------
// Kernel 1: routing MLP + softmax.  64 blocks x 64 threads.
// ---------------------------------------------------------------------------
__global__ void routing_kernel(const float* __restrict__ cond,
                               const float* __restrict__ w1,
                               const float* __restrict__ w2) {
    __shared__ float sh[HIDDEN];
    __shared__ float sl[KEXP];
    const int b = blockIdx.x;
    const int j = threadIdx.x;

    const float* crow = cond + b * CS;
    const float* w1r  = w1 + j * CS;
    float s = 0.0f;
#pragma unroll 8
    for (int i = 0; i < CS; ++i) s = fmaf(crow[i], w1r[i], s);
    sh[j] = fmaxf(s, 0.0f);
    __syncthreads();

    if (j < KEXP) {
        const float* w2r = w2 + j * HIDDEN;
        float t = 0.0f;
#pragma unroll 8
        for (int i = 0; i < HIDDEN; ++i) t = fmaf(sh[i], w2r[i], t);
        sl[j] = t * (1.0f / TEMP);
    }
    __syncthreads();

    if (j == 0) {
        float m = sl[0];
#pragma unroll
        for (int k = 1; k < KEXP; ++k) m = fmaxf(m, sl[k]);
        float e[KEXP];
        float sum = 0.0f;
#pragma unroll
        for (int k = 0; k < KEXP; ++k) { e[k] = expf(sl[k] - m); sum += e[k]; }
        float inv = 1.0f / sum;
#pragma unroll
        for (int k = 0; k < KEXP; ++k) g_att[b * KEXP + k] = e[k] * inv;
    }
}

// ---------------------------------------------------------------------------
// Kernel 2: transpose kw=1 slice -> Wt[k][ci][kh][o]
// ---------------------------------------------------------------------------
__global__ void build_wt_kernel(const float* __restrict__ weight) {
    const int i  = blockIdx.x * 256 + threadIdx.x;
    const int o  = i & (COUT - 1);
    const int t  = i >> 8;           // (k*CIN + ci)*3 + kh
    const int kh = t % 3;
    const int t2 = t / 3;
    const int ci = t2 & (CIN - 1);
    const int k  = t2 >> 8;
    g_wt[i] = weight[(((k * COUT + o) * CIN + ci) * 3 + kh) * 3 + 1];
}

// ---------------------------------------------------------------------------
// Kernel 3: conv with packed f32x2 FMAs.
// grid (2 h-tiles, 8 o-tiles, 64 batch), 256 threads.
// Thread = (og = tid>>5 -> 4 couts, hg = tid&31 -> 8 h-PAIRS strided by 32).
// s_x [j] = x[h_base-1+j]  (A,C taps are even-aligned float2)
// s_xs[j] = x[h_base  +j]  (B tap even-aligned float2)
// ---------------------------------------------------------------------------
__global__ void __launch_bounds__(256, 2)
conv_kernel(const float* __restrict__ x,
            const float* __restrict__ bias,
            float* __restrict__ out) {
    __shared__ float s_x [CCH * SXSTR];   // 16448 B
    __shared__ float s_xs[CCH * SXSTR];   // 16448 B
    __shared__ float s_w [CCH * 3 * TO];  //  3072 B

    const int tid    = threadIdx.x;
    const int hg     = tid & 31;
    const int og4    = (tid >> 5) * 4;
    const int h_base = blockIdx.x * TH;
    const int o_base = blockIdx.y * TO;
    const int b      = blockIdx.z;

    float att4[KEXP];
#pragma unroll
    for (int k = 0; k < KEXP; ++k) att4[k] = g_att[b * KEXP + k];

    const float* xb = x + (size_t)b * CIN * LEN;

    unsigned long long acc[4][8];
#pragma unroll
    for (int u = 0; u < 4; ++u)
#pragma unroll
        for (int p = 0; p < 8; ++p) acc[u][p] = 0ULL;

    for (int cb = 0; cb < CIN; cb += CCH) {
        __syncthreads();   // previous iteration's smem reads done

        // stage x chunk (halo both sides) + shifted copy
        for (int i = tid; i < CCH * SXSTR; i += 256) {
            int ci = i / SXSTR;
            int hh = i - ci * SXSTR;
            int hs = h_base - 1 + hh;
            float v = 0.0f;
            if ((unsigned)hs < (unsigned)LEN) v = xb[(cb + ci) * LEN + hs];
            s_x[i] = v;
            if (hh > 0) s_xs[i - 1] = v;
        }

        // mix expert weights for this (cout tile, cin chunk)
        for (int i = tid; i < CCH * 3 * TO; i += 256) {
            int o  = i & (TO - 1);
            int t  = i >> 5;          // ci*3 + kh
            int kh = t % 3;
            int ci = t / 3;
            const float* wp = g_wt + ((cb + ci) * 3 + kh) * COUT + o_base + o;
            s_w[i] = att4[0] * wp[0 * CIN * 3 * COUT]
                   + att4[1] * wp[1 * CIN * 3 * COUT]
                   + att4[2] * wp[2 * CIN * 3 * COUT]
                   + att4[3] * wp[3 * CIN * 3 * COUT];
        }
        __syncthreads();

#pragma unroll
        for (int ci = 0; ci < CCH; ++ci) {
            unsigned long long wA[4], wB[4], wC[4];
#pragma unroll
            for (int u = 0; u < 4; ++u) {
                wA[u] = splat2(s_w[(ci * 3 + 0) * TO + og4 + u]);
                wB[u] = splat2(s_w[(ci * 3 + 1) * TO + og4 + u]);
                wC[u] = splat2(s_w[(ci * 3 + 2) * TO + og4 + u]);
            }
            const float* xr  = s_x  + ci * SXSTR;
            const float* xrs = s_xs + ci * SXSTR;
#pragma unroll
            for (int p = 0; p < 8; ++p) {
                const int hl = 2 * hg + 64 * p;          // even
                unsigned long long A  = *(const unsigned long long*)(xr  + hl);      // x[h-1],x[h]
                unsigned long long Bv = *(const unsigned long long*)(xrs + hl);      // x[h],  x[h+1]
                unsigned long long Cv = *(const unsigned long long*)(xr  + hl + 2);  // x[h+1],x[h+2]
#pragma unroll
                for (int u = 0; u < 4; ++u)
                    acc[u][p] = fma2(wA[u], A, fma2(wB[u], Bv, fma2(wC[u], Cv, acc[u][p])));
            }
        }
    }

    // epilogue: add mixed bias, store as float2 (coalesced, aligned)
#pragma unroll
    for (int u = 0; u < 4; ++u) {
        const int o = o_base + og4 + u;
        float bs = 0.0f;
#pragma unroll
        for (int k = 0; k < KEXP; ++k) bs = fmaf(att4[k], bias[k * COUT + o], bs);
        float* op = out + ((size_t)(b * COUT + o)) * LEN + h_base;
#pragma unroll
        for (int p = 0; p < 8; ++p) {
            float2 v = *(float2*)&acc[u][p];
            v.x += bs; v.y += bs;
            *(float2*)(op + 2 * hg + 64 * p) = v;
        }
    }
}

// ---------------------------------------------------------------------------
extern "C" void kernel_launch(void* const* d_in, const int* in_sizes, int n_in,
                              void* d_out, int out_size) {
    const float* x      = (const float*)d_in[0];   // (64,256,1024,1)
    const float* cond   = (const float*)d_in[1];   // (64,256)
    const float* w1     = (const float*)d_in[2];   // (64,256)
    const float* w2     = (const float*)d_in[3];   // (4,64)
    const float* weight = (const float*)d_in[4];   // (4,256,256,3,3)
    const float* bias   = (const float*)d_in[5];   // (4,256)
    float* out = (float*)d_out;                    // (64,256,1024,1)

    routing_kernel<<<BATCH, HIDDEN>>>(cond, w1, w2);
    build_wt_kernel<<<(KEXP * CIN * 3 * COUT) / 256, 256>>>(weight);
    conv_kernel<<<dim3(LEN / TH, COUT / TO, BATCH), 256>>>(x, bias, out);
}

// round 8
// speedup vs baseline: 2.9795x; 2.2771x over previous
#include <cuda_runtime.h>
#include <cuda_bf16.h>
#include <mma.h>
#include <cstdint>

using namespace nvcuda;

// DynamicConv: B=64, CIN=COUT=256, K=4 experts, 3x3 kernel on (L=1024 x 1).
// Width==1 + padding 1 => only kw=1 column contributes: per-batch GEMM
//   C[o,h] = sum_{ci,kh} Wagg[b][o,ci,kh] * x[b][ci,h-1+kh]   (M=256,N=1024,K=768)
// wmma bf16 (HMMA) path, 3-pass hi/lo split, fp32 accumulate.
// Bias folded in as an extra K=16 GEMM term -> direct global store.

#define BATCH   64
#define CIN     256
#define COUT    256
#define CS      256
#define KEXP    4
#define HIDDEN  64
#define LEN     1024
#define TEMP    30.0f

#define TM      128            // o per CTA
#define TN      128            // h per CTA
#define CCH     64             // ci per K-chunk
#define NCB     (CIN / CCH)    // 4

#define ASTR    72             // bf16 A row stride (64 + 8 pad -> conflict-free LDSM)
#define BSTR    72             // bf16 B row stride
#define XSTR    133            // fp32 x_s row stride (odd -> conflict-free transpose)
#define BBSTR   24             // bias tile stride

// SMEM byte offsets (x_s overlays the A region: disjoint lifetimes)
#define SM_AHI   0                          // A hi  128x72 bf16 = 18432
#define SM_ALO   18432                      // A lo
#define SM_BHI   36864                      // B hi  132x72 bf16 = 19008
#define SM_BLO   (36864 + 19008)            // 55872
#define SM_ABH   (55872 + 19008)            // 74880  bias A hi 128x24 = 6144
#define SM_ABL   (74880 + 6144)             // 81024  bias A lo
#define SM_BB    (81024 + 6144)             // 87168  bias B     128x24 = 6144
#define SM_TOTAL (87168 + 6144)             // 93312

__device__ float g_att[BATCH * KEXP];
__device__ float g_bmix[BATCH * COUT];
// Wagg bf16 split: [b][kh][cbi][o(256)][ci(64)]
#define WA_BSTRIDE (3 * NCB * COUT * CCH)   // 196608
__device__ __nv_bfloat16 g_wa_hi[BATCH * WA_BSTRIDE];
__device__ __nv_bfloat16 g_wa_lo[BATCH * WA_BSTRIDE];

// ---------------------------------------------------------------------------
// Kernel 1: routing MLP + softmax.
// ---------------------------------------------------------------------------
__global__ void routing_kernel(const float* __restrict__ cond,
                               const float* __restrict__ w1,
                               const float* __restrict__ w2) {
    __shared__ float sh[HIDDEN];
    __shared__ float sl[KEXP];
    const int b = blockIdx.x;
    const int j = threadIdx.x;

    const float* crow = cond + b * CS;
    const float* w1r  = w1 + j * CS;
    float s = 0.0f;
#pragma unroll 8
    for (int i = 0; i < CS; ++i) s = fmaf(crow[i], w1r[i], s);
    sh[j] = fmaxf(s, 0.0f);
    __syncthreads();

    if (j < KEXP) {
        const float* w2r = w2 + j * HIDDEN;
        float t = 0.0f;
#pragma unroll 8
        for (int i = 0; i < HIDDEN; ++i) t = fmaf(sh[i], w2r[i], t);
        sl[j] = t * (1.0f / TEMP);
    }
    __syncthreads();

    if (j == 0) {
        float m = sl[0];
#pragma unroll
        for (int k = 1; k < KEXP; ++k) m = fmaxf(m, sl[k]);
        float e[KEXP];
        float sum = 0.0f;
#pragma unroll
        for (int k = 0; k < KEXP; ++k) { e[k] = expf(sl[k] - m); sum += e[k]; }
        float inv = 1.0f / sum;
#pragma unroll
        for (int k = 0; k < KEXP; ++k) g_att[b * KEXP + k] = e[k] * inv;
    }
}

// ---------------------------------------------------------------------------
// Kernel 2: mix experts + bf16 hi/lo split -> g_wa_hi/lo[b][kh][cbi][o][ci]
// ---------------------------------------------------------------------------
__global__ void mix_kernel(const float* __restrict__ weight) {
    const int idx = blockIdx.x * 256 + threadIdx.x;   // 0 .. 3*4*256*64-1
    const int ci  = idx & 63;
    const int o   = (idx >> 6) & 255;
    const int cbi = (idx >> 14) & 3;
    const int kh  = idx >> 16;                        // 0..2
    const int cig = cbi * CCH + ci;

    float w4[KEXP];
#pragma unroll
    for (int k = 0; k < KEXP; ++k)
        w4[k] = weight[(((k * COUT + o) * CIN + cig) * 3 + kh) * 3 + 1];

    const size_t obase = (((size_t)kh * NCB + cbi) * COUT + o) * CCH + ci;
    for (int b = 0; b < BATCH; ++b) {
        const float* a = g_att + b * KEXP;
        float v = a[0] * w4[0] + a[1] * w4[1] + a[2] * w4[2] + a[3] * w4[3];
        __nv_bfloat16 h = __float2bfloat16(v);
        float lo = v - __bfloat162float(h);
        g_wa_hi[(size_t)b * WA_BSTRIDE + obase] = h;
        g_wa_lo[(size_t)b * WA_BSTRIDE + obase] = __float2bfloat16(lo);
    }
}

// ---------------------------------------------------------------------------
// Kernel 2b: mixed bias.
// ---------------------------------------------------------------------------
__global__ void bmix_kernel(const float* __restrict__ bias) {
    const int b = blockIdx.x;
    const int o = threadIdx.x;
    const float* a = g_att + b * KEXP;
    float v = 0.0f;
#pragma unroll
    for (int k = 0; k < KEXP; ++k) v = fmaf(a[k], bias[k * COUT + o], v);
    g_bmix[b * COUT + o] = v;
}

// ---------------------------------------------------------------------------
// Kernel 3: wmma conv. grid (8 h-tiles, 2 o-tiles, 64 b), 256 threads.
// Warp (wm 0..3, wn 0..1): tile 32(o) x 64(h) = acc[2][4] of 16x16.
// ---------------------------------------------------------------------------
__global__ void __launch_bounds__(256, 2)
conv_kernel(const float* __restrict__ x, float* __restrict__ out) {
    extern __shared__ char smem[];
    const int tid = threadIdx.x;
    const int wid = tid >> 5;
    const int lid = tid & 31;
    const int hb  = blockIdx.x * TN;
    const int ob  = blockIdx.y * TM;
    const int b   = blockIdx.z;
    const int wm  = wid >> 1;     // 0..3 -> 32 o-rows
    const int wn  = wid & 1;      // 0..1 -> 64 h-cols

    float* x_s = (float*)(smem);  // overlays A region

    wmma::fragment<wmma::accumulator, 16, 16, 16, float> acc[2][4];
#pragma unroll
    for (int mt = 0; mt < 2; ++mt)
#pragma unroll
        for (int nt = 0; nt < 4; ++nt) wmma::fill_fragment(acc[mt][nt], 0.0f);

    // ---- bias tiles: A col0 = bmix hi/lo, B col0 = 1.0 ----
    for (int i = tid; i < (3 * 6144) / 4; i += 256)
        ((uint32_t*)(smem + SM_ABH))[i] = 0;
    __syncthreads();
    if (tid < 128) {
        float bm = g_bmix[b * COUT + ob + tid];
        __nv_bfloat16 h = __float2bfloat16(bm);
        ((__nv_bfloat16*)(smem + SM_ABH))[tid * BBSTR] = h;
        ((__nv_bfloat16*)(smem + SM_ABL))[tid * BBSTR] = __float2bfloat16(bm - __bfloat162float(h));
        ((__nv_bfloat16*)(smem + SM_BB ))[tid * BBSTR] = __float2bfloat16(1.0f);
    }
    __syncthreads();
    {
        wmma::fragment<wmma::matrix_a, 16, 16, 16, __nv_bfloat16, wmma::row_major> fa;
        wmma::fragment<wmma::matrix_b, 16, 16, 16, __nv_bfloat16, wmma::col_major> fb[4];
#pragma unroll
        for (int nt = 0; nt < 4; ++nt)
            wmma::load_matrix_sync(fb[nt],
                (const __nv_bfloat16*)(smem + SM_BB) + (wn * 64 + nt * 16) * BBSTR, BBSTR);
#pragma unroll
        for (int mt = 0; mt < 2; ++mt) {
            wmma::load_matrix_sync(fa,
                (const __nv_bfloat16*)(smem + SM_ABH) + (wm * 32 + mt * 16) * BBSTR, BBSTR);
#pragma unroll
            for (int nt = 0; nt < 4; ++nt) wmma::mma_sync(acc[mt][nt], fa, fb[nt], acc[mt][nt]);
            wmma::load_matrix_sync(fa,
                (const __nv_bfloat16*)(smem + SM_ABL) + (wm * 32 + mt * 16) * BBSTR, BBSTR);
#pragma unroll
            for (int nt = 0; nt < 4; ++nt) wmma::mma_sync(acc[mt][nt], fa, fb[nt], acc[mt][nt]);
        }
    }
    __syncthreads();   // bias-region fragment loads done before x_s staging below

    const float* xb = x + (size_t)b * CIN * LEN;

    for (int cbi = 0; cbi < NCB; ++cbi) {
        // ---- stage x chunk fp32 (overlays A region; prior mma synced) ----
        for (int idx = tid; idx < CCH * 130; idx += 256) {
            int ci = idx / 130;
            int n  = idx - ci * 130;
            int hs = hb - 1 + n;
            float v = 0.0f;
            if ((unsigned)hs < (unsigned)LEN) v = xb[(cbi * CCH + ci) * LEN + hs];
            x_s[ci * XSTR + n] = v;
        }
        __syncthreads();

        // ---- build B tiles [n=h_in][k=ci] bf16 hi/lo (shared across 3 kh) ----
        for (int n = wid; n < 130; n += 8) {
            float v0 = x_s[(2 * lid    ) * XSTR + n];
            float v1 = x_s[(2 * lid + 1) * XSTR + n];
            __nv_bfloat16 h0 = __float2bfloat16(v0);
            __nv_bfloat16 h1 = __float2bfloat16(v1);
            __nv_bfloat162 hh; hh.x = h0; hh.y = h1;
            __nv_bfloat162 ll;
            ll.x = __float2bfloat16(v0 - __bfloat162float(h0));
            ll.y = __float2bfloat16(v1 - __bfloat162float(h1));
            *(__nv_bfloat162*)(smem + SM_BHI + n * (BSTR * 2) + lid * 4) = hh;
            *(__nv_bfloat162*)(smem + SM_BLO + n * (BSTR * 2) + lid * 4) = ll;
        }
        __syncthreads();

        for (int kh = 0; kh < 3; ++kh) {
            // ---- stage A hi/lo (overwrites x_s region; prior readers synced) ----
            const uint4* gh = (const uint4*)(g_wa_hi +
                ((((size_t)b * 3 + kh) * NCB + cbi) * COUT + ob) * CCH);
            const uint4* gl = (const uint4*)(g_wa_lo +
                ((((size_t)b * 3 + kh) * NCB + cbi) * COUT + ob) * CCH);
#pragma unroll
            for (int t = 0; t < 4; ++t) {
                int idx = tid + t * 256;          // 1024 uint4 = 128 rows x 8
                int r = idx >> 3, c = idx & 7;
                *(uint4*)(smem + SM_AHI + r * (ASTR * 2) + c * 16) = gh[idx];
                *(uint4*)(smem + SM_ALO + r * (ASTR * 2) + c * 16) = gl[idx];
            }
            __syncthreads();

            const __nv_bfloat16* Ah = (const __nv_bfloat16*)(smem + SM_AHI);
            const __nv_bfloat16* Al = (const __nv_bfloat16*)(smem + SM_ALO);
            const __nv_bfloat16* Bh = (const __nv_bfloat16*)(smem + SM_BHI);
            const __nv_bfloat16* Bl = (const __nv_bfloat16*)(smem + SM_BLO);

#pragma unroll
            for (int ks = 0; ks < 4; ++ks) {
                wmma::fragment<wmma::matrix_a, 16, 16, 16, __nv_bfloat16, wmma::row_major> fah[2], fal[2];
                wmma::fragment<wmma::matrix_b, 16, 16, 16, __nv_bfloat16, wmma::col_major> fbx[4];
#pragma unroll
                for (int mt = 0; mt < 2; ++mt)
                    wmma::load_matrix_sync(fah[mt], Ah + (wm * 32 + mt * 16) * ASTR + ks * 16, ASTR);
                // pass 1: Ah * Bh
#pragma unroll
                for (int nt = 0; nt < 4; ++nt)
                    wmma::load_matrix_sync(fbx[nt], Bh + (wn * 64 + nt * 16 + kh) * BSTR + ks * 16, BSTR);
#pragma unroll
                for (int mt = 0; mt < 2; ++mt)
#pragma unroll
                    for (int nt = 0; nt < 4; ++nt)
                        wmma::mma_sync(acc[mt][nt], fah[mt], fbx[nt], acc[mt][nt]);
                // pass 2: Al * Bh  (Bh frags still live)
#pragma unroll
                for (int mt = 0; mt < 2; ++mt)
                    wmma::load_matrix_sync(fal[mt], Al + (wm * 32 + mt * 16) * ASTR + ks * 16, ASTR);
#pragma unroll
                for (int mt = 0; mt < 2; ++mt)
#pragma unroll
                    for (int nt = 0; nt < 4; ++nt)
                        wmma::mma_sync(acc[mt][nt], fal[mt], fbx[nt], acc[mt][nt]);
                // pass 3: Ah * Bl
#pragma unroll
                for (int nt = 0; nt < 4; ++nt)
                    wmma::load_matrix_sync(fbx[nt], Bl + (wn * 64 + nt * 16 + kh) * BSTR + ks * 16, BSTR);
#pragma unroll
                for (int mt = 0; mt < 2; ++mt)
#pragma unroll
                    for (int nt = 0; nt < 4; ++nt)
                        wmma::mma_sync(acc[mt][nt], fah[mt], fbx[nt], acc[mt][nt]);
            }
            __syncthreads();   // fragment loads done before next A restage / x_s restage
        }
    }

    // ---- epilogue: bias already in acc; store straight to global ----
    float* op = out + ((size_t)(b * COUT + ob + wm * 32)) * LEN + hb + wn * 64;
#pragma unroll
    for (int mt = 0; mt < 2; ++mt)
#pragma unroll
        for (int nt = 0; nt < 4; ++nt)
            wmma::store_matrix_sync(op + (size_t)mt * 16 * LEN + nt * 16,
                                    acc[mt][nt], LEN, wmma::mem_row_major);
}

// ---------------------------------------------------------------------------
extern "C" void kernel_launch(void* const* d_in, const int* in_sizes, int n_in,
                              void* d_out, int out_size) {
    const float* x      = (const float*)d_in[0];   // (64,256,1024,1)
    const float* cond   = (const float*)d_in[1];   // (64,256)
    const float* w1     = (const float*)d_in[2];   // (64,256)
    const float* w2     = (const float*)d_in[3];   // (4,64)
    const float* weight = (const float*)d_in[4];   // (4,256,256,3,3)
    const float* bias   = (const float*)d_in[5];   // (4,256)
    float* out = (float*)d_out;                    // (64,256,1024,1)

    static int attr_set = 0;
    if (!attr_set) {
        cudaFuncSetAttribute(conv_kernel,
                             cudaFuncAttributeMaxDynamicSharedMemorySize, SM_TOTAL);
        attr_set = 1;
    }

    routing_kernel<<<BATCH, HIDDEN>>>(cond, w1, w2);
    mix_kernel<<<(3 * NCB * COUT * CCH) / 256, 256>>>(weight);
    bmix_kernel<<<BATCH, COUT>>>(bias);
    conv_kernel<<<dim3(LEN / TN, COUT / TM, BATCH), 256, SM_TOTAL>>>(x, out);
}